// round 17
// baseline (speedup 1.0000x reference)
#include <cuda_runtime.h>
#include <cuda_fp16.h>
#include <cstdint>
#include <math.h>

#define NB   4
#define NC   256
#define NPIX 4096

// ================= scratch (no allocations allowed) =================
__device__ __align__(128) __half g_xs_hi[(size_t)NB*NPIX*NC];   // x_self^T [n][c]
__device__ __align__(128) __half g_xo_hi[(size_t)NB*NPIX*NC];   // x_other^T [n][c]
__device__ __align__(128) __half g_qt_hi[(size_t)NB*NPIX*NC];   // Q^T [n][c]
__device__ __align__(128) __half g_kt_hi[(size_t)NB*NPIX*NC];   // K^T [m][c]
__device__ __align__(128) __half g_v_hi [(size_t)NB*NC*NPIX];   // V [c][m]
__device__ __align__(128) __half g_p    [(size_t)NB*NPIX*NPIX]; // exp(S) [n][m] fp16
__device__ __align__(128) __half g_fusedh[(size_t)NB*NC*NPIX];  // local, then fused [c][n] fp16
__device__ __align__(128) __half g_ft_hi[(size_t)NB*NPIX*NC];   // fused^T [n][c]
__device__ __align__(128) __half g_qw_hi[NC*NC];
__device__ __align__(128) __half g_kvw_hi[2*NC*NC];
__device__ __align__(128) __half g_ow_hi[NC*NC];
__device__ float g_rowsum[NB*NPIX];   // per-row sums of exp(S)
__device__ float g_pool[NB*NC];       // per-channel sums of x_self
__device__ float g_gate[NB];

// ================= helpers =================
__device__ __forceinline__ uint32_t smem_u32(const void* p) {
    uint32_t a;
    asm("{ .reg .u64 t; cvta.to.shared.u64 t, %1; cvt.u32.u64 %0, t; }" : "=r"(a) : "l"(p));
    return a;
}
__device__ __forceinline__ void ldm_x4(uint32_t* r, uint32_t addr) {
    asm volatile("ldmatrix.sync.aligned.m8n8.x4.shared.b16 {%0,%1,%2,%3}, [%4];"
        : "=r"(r[0]), "=r"(r[1]), "=r"(r[2]), "=r"(r[3]) : "r"(addr));
}
__device__ __forceinline__ void mma_f16(float* d, const uint32_t* a, uint32_t b0, uint32_t b1) {
    asm volatile("mma.sync.aligned.m16n8k16.row.col.f32.f16.f16.f32 "
        "{%0,%1,%2,%3}, {%4,%5,%6,%7}, {%8,%9}, {%0,%1,%2,%3};"
        : "+f"(d[0]), "+f"(d[1]), "+f"(d[2]), "+f"(d[3])
        : "r"(a[0]), "r"(a[1]), "r"(a[2]), "r"(a[3]), "r"(b0), "r"(b1));
}
#define CP_ASYNC16(saddr, gptr) \
    asm volatile("cp.async.cg.shared.global [%0], [%1], 16;" :: "r"(saddr), "l"(gptr))
#define CP_COMMIT() asm volatile("cp.async.commit_group;" ::: "memory")
#define CP_WAIT0()  asm volatile("cp.async.wait_group 0;" ::: "memory")

__device__ __forceinline__ uint32_t swz(uint32_t o) { return o ^ ((o >> 3) & 0x70); }

#define A_TILE  16384
#define SMTOT1  (2 * 2 * A_TILE)              // 65536

__device__ __forceinline__ void cp_tile(uint32_t dst, const __half* src, int K, int tid) {
    #pragma unroll
    for (int r = 0; r < 4; r++) {
        int idx = tid + (r << 8);
        int row = idx >> 3, cc = idx & 7;
        CP_ASYNC16(dst + swz(row * 128 + cc * 16), src + (size_t)row * K + cc * 8);
    }
}

// ================= generic 1-term GEMM =================
// D[m][n] = alpha*sum_k A[m][k]*B[n][k] (+bias)
// BIAS_MODE: 0 none, 1 per-row (M), 3 col-scale by 1/g_rowsum[n].
// OUT_MODE:  0 fp32, 2 fp16, 3 fp16 exp() + atomic row-sum,
//            4 fp16 fused: Ch[r][c] = Ch_old[r][c] + gate[z] * v  (in-place local+gate*O)
template<int BIAS_MODE, int OUT_MODE>
__global__ __launch_bounds__(256, 2)
void mma_gemm(const __half* __restrict__ Ah, const __half* __restrict__ Bh,
              const float* __restrict__ bias, float alpha,
              float* __restrict__ Cf, __half* __restrict__ Ch,
              int K, int ldc, long long sA, long long sB, long long sC)
{
    constexpr uint32_t STG = 2 * A_TILE;
    extern __shared__ __align__(1024) char dsm[];
    const uint32_t sb = smem_u32(dsm);
    const int tid = threadIdx.x, wid = tid >> 5, lane = tid & 31;
    const int warp_m = wid & 3, warp_n = wid >> 2;

    const size_t m0 = (size_t)blockIdx.y << 7;
    const size_t n0 = (size_t)blockIdx.x << 7;
    const __half* pah = Ah + (long long)blockIdx.z * sA + m0 * K;
    const __half* pbh = Bh + (long long)blockIdx.z * sB + n0 * K;

    float acc[2][8][4];
    #pragma unroll
    for (int i = 0; i < 2; i++)
        #pragma unroll
        for (int j = 0; j < 8; j++)
            #pragma unroll
            for (int q = 0; q < 4; q++) acc[i][j][q] = 0.f;

    const int nch = K >> 6;
    cp_tile(sb, pah, K, tid);
    cp_tile(sb + A_TILE, pbh, K, tid);
    CP_COMMIT();

    for (int ch = 0; ch < nch; ch++) {
        CP_WAIT0();
        __syncthreads();
        if (ch + 1 < nch) {
            const size_t k0 = (size_t)(ch + 1) << 6;
            const uint32_t nb = sb + ((ch + 1) & 1) * STG;
            cp_tile(nb, pah + k0, K, tid);
            cp_tile(nb + A_TILE, pbh + k0, K, tid);
            CP_COMMIT();
        }
        const uint32_t cbAH = sb + (ch & 1) * STG;
        const uint32_t cbBH = cbAH + A_TILE;

        #pragma unroll
        for (int ks = 0; ks < 4; ks++) {
            const uint32_t koff = ks * 32 + (lane >> 4) * 16;
            uint32_t a_hi[2][4];
            #pragma unroll
            for (int im = 0; im < 2; im++) {
                uint32_t off = swz((warp_m * 32 + im * 16 + (lane & 15)) * 128 + koff);
                ldm_x4(a_hi[im], cbAH + off);
            }
            #pragma unroll
            for (int in2 = 0; in2 < 4; in2++) {
                uint32_t off = swz((warp_n * 64 + in2 * 16 + (lane & 15)) * 128 + koff);
                uint32_t bh[4];
                ldm_x4(bh, cbBH + off);
                #pragma unroll
                for (int im = 0; im < 2; im++) {
                    #pragma unroll
                    for (int s = 0; s < 2; s++)
                        mma_f16(acc[im][in2 * 2 + s], a_hi[im], bh[s], bh[s + 2]);
                }
            }
        }
        __syncthreads();
    }

    // ---------------- epilogue ----------------
    const long long cbase = (long long)blockIdx.z * sC;
    const long long zrs = (long long)blockIdx.z * NPIX;
    const float gate = (OUT_MODE == 4) ? g_gate[blockIdx.z] : 0.f;
    #pragma unroll
    for (int im = 0; im < 2; im++) {
        const int r0 = (int)m0 + warp_m * 32 + im * 16 + (lane >> 2);
        const int r1 = r0 + 8;
        float rb0 = 0.f, rb1 = 0.f;
        if (BIAS_MODE == 1) { rb0 = bias[r0]; rb1 = bias[r1]; }
        float esum0 = 0.f, esum1 = 0.f;
        #pragma unroll
        for (int in = 0; in < 8; in++) {
            const int c = (int)n0 + warp_n * 64 + in * 8 + (lane & 3) * 2;
            float v0 = fmaf(alpha, acc[im][in][0], rb0);
            float v1 = fmaf(alpha, acc[im][in][1], rb0);
            float v2 = fmaf(alpha, acc[im][in][2], rb1);
            float v3 = fmaf(alpha, acc[im][in][3], rb1);
            if (BIAS_MODE == 3) {
                float i0 = __fdividef(1.f, g_rowsum[zrs + c]);
                float i1 = __fdividef(1.f, g_rowsum[zrs + c + 1]);
                v0 *= i0; v1 *= i1; v2 *= i0; v3 *= i1;
            }
            if (OUT_MODE == 3) {
                __half h0 = __float2half(__expf(v0));
                __half h1 = __float2half(__expf(v1));
                __half h2 = __float2half(__expf(v2));
                __half h3 = __float2half(__expf(v3));
                esum0 += __half2float(h0) + __half2float(h1);
                esum1 += __half2float(h2) + __half2float(h3);
                *reinterpret_cast<__half2*>(Ch + cbase + (size_t)r0 * ldc + c) = __halves2half2(h0, h1);
                *reinterpret_cast<__half2*>(Ch + cbase + (size_t)r1 * ldc + c) = __halves2half2(h2, h3);
            } else if (OUT_MODE == 4) {
                __half2* p0 = reinterpret_cast<__half2*>(Ch + cbase + (size_t)r0 * ldc + c);
                __half2* p1 = reinterpret_cast<__half2*>(Ch + cbase + (size_t)r1 * ldc + c);
                float2 l0 = __half22float2(*p0);
                float2 l1 = __half22float2(*p1);
                *p0 = __floats2half2_rn(fmaf(gate, v0, l0.x), fmaf(gate, v1, l0.y));
                *p1 = __floats2half2_rn(fmaf(gate, v2, l1.x), fmaf(gate, v3, l1.y));
            } else if (OUT_MODE == 2) {
                *reinterpret_cast<__half2*>(Ch + cbase + (size_t)r0 * ldc + c) =
                    __halves2half2(__float2half(v0), __float2half(v1));
                *reinterpret_cast<__half2*>(Ch + cbase + (size_t)r1 * ldc + c) =
                    __halves2half2(__float2half(v2), __float2half(v3));
            } else {
                *reinterpret_cast<float2*>(Cf + cbase + (size_t)r0 * ldc + c) = make_float2(v0, v1);
                *reinterpret_cast<float2*>(Cf + cbase + (size_t)r1 * ldc + c) = make_float2(v2, v3);
            }
        }
        if (OUT_MODE == 3) {
            esum0 += __shfl_xor_sync(0xffffffffu, esum0, 1);
            esum0 += __shfl_xor_sync(0xffffffffu, esum0, 2);
            esum1 += __shfl_xor_sync(0xffffffffu, esum1, 1);
            esum1 += __shfl_xor_sync(0xffffffffu, esum1, 2);
            if ((lane & 3) == 0) {
                atomicAdd(&g_rowsum[zrs + r0], esum0);
                atomicAdd(&g_rowsum[zrs + r1], esum1);
            }
        }
    }
}

// ================= merged Q/K/V projection GEMM =================
// grid (64, 1, 12): z>>2 = role (0 Q, 1 K, 2 V), z&3 = batch.
__global__ __launch_bounds__(256, 2)
void proj_gemm(const __half* __restrict__ xs, const __half* __restrict__ xo,
               const __half* __restrict__ qw, const __half* __restrict__ kvw,
               const float* __restrict__ q_b, const float* __restrict__ kv_b,
               __half* __restrict__ qt, __half* __restrict__ kt, __half* __restrict__ v)
{
    constexpr uint32_t STG = 2 * A_TILE;
    extern __shared__ __align__(1024) char dsm[];
    const uint32_t sb = smem_u32(dsm);
    const int tid = threadIdx.x, wid = tid >> 5, lane = tid & 31;
    const int warp_m = wid & 3, warp_n = wid >> 2;
    const int role = blockIdx.z >> 2, b = blockIdx.z & 3;
    const int bx = blockIdx.x;
    const long long sX = (long long)NPIX * NC;

    const __half *Ah, *Bh;
    const float* bias;
    __half* Ch;
    int ldc;
    bool colBias;
    size_t m0, n0;
    if (role == 0) {
        Ah = xs + b * sX; Bh = qw; bias = q_b; Ch = qt + b * sX;
        ldc = NC; colBias = true;
        m0 = (size_t)(bx >> 1) << 7; n0 = (size_t)(bx & 1) << 7;
    } else if (role == 1) {
        Ah = xo + b * sX; Bh = kvw; bias = kv_b; Ch = kt + b * sX;
        ldc = NC; colBias = true;
        m0 = (size_t)(bx >> 1) << 7; n0 = (size_t)(bx & 1) << 7;
    } else {
        Ah = kvw + NC * NC; Bh = xo + b * sX; bias = kv_b + NC; Ch = v + b * sX;
        ldc = NPIX; colBias = false;
        m0 = (size_t)(bx & 1) << 7; n0 = (size_t)(bx >> 1) << 7;
    }
    const __half* pah = Ah + m0 * NC;
    const __half* pbh = Bh + n0 * NC;

    float acc[2][8][4];
    #pragma unroll
    for (int i = 0; i < 2; i++)
        #pragma unroll
        for (int j = 0; j < 8; j++)
            #pragma unroll
            for (int q = 0; q < 4; q++) acc[i][j][q] = 0.f;

    cp_tile(sb, pah, NC, tid);
    cp_tile(sb + A_TILE, pbh, NC, tid);
    CP_COMMIT();

    const int nch = NC >> 6;   // 4
    for (int ch = 0; ch < nch; ch++) {
        CP_WAIT0();
        __syncthreads();
        if (ch + 1 < nch) {
            const size_t k0 = (size_t)(ch + 1) << 6;
            const uint32_t nb = sb + ((ch + 1) & 1) * STG;
            cp_tile(nb, pah + k0, NC, tid);
            cp_tile(nb + A_TILE, pbh + k0, NC, tid);
            CP_COMMIT();
        }
        const uint32_t cbAH = sb + (ch & 1) * STG;
        const uint32_t cbBH = cbAH + A_TILE;

        #pragma unroll
        for (int ks = 0; ks < 4; ks++) {
            const uint32_t koff = ks * 32 + (lane >> 4) * 16;
            uint32_t a_hi[2][4];
            #pragma unroll
            for (int im = 0; im < 2; im++) {
                uint32_t off = swz((warp_m * 32 + im * 16 + (lane & 15)) * 128 + koff);
                ldm_x4(a_hi[im], cbAH + off);
            }
            #pragma unroll
            for (int in2 = 0; in2 < 4; in2++) {
                uint32_t off = swz((warp_n * 64 + in2 * 16 + (lane & 15)) * 128 + koff);
                uint32_t bh[4];
                ldm_x4(bh, cbBH + off);
                #pragma unroll
                for (int im = 0; im < 2; im++) {
                    #pragma unroll
                    for (int s = 0; s < 2; s++)
                        mma_f16(acc[im][in2 * 2 + s], a_hi[im], bh[s], bh[s + 2]);
                }
            }
        }
        __syncthreads();
    }

    // epilogue: fp16 out, runtime row/col bias
    #pragma unroll
    for (int im = 0; im < 2; im++) {
        const int r0 = (int)m0 + warp_m * 32 + im * 16 + (lane >> 2);
        const int r1 = r0 + 8;
        float rb0 = 0.f, rb1 = 0.f;
        if (!colBias) { rb0 = bias[r0]; rb1 = bias[r1]; }
        #pragma unroll
        for (int in = 0; in < 8; in++) {
            const int c = (int)n0 + warp_n * 64 + in * 8 + (lane & 3) * 2;
            float cb0, cb1, cb2, cb3;
            if (colBias) { cb0 = cb2 = bias[c]; cb1 = cb3 = bias[c + 1]; }
            else         { cb0 = cb1 = rb0; cb2 = cb3 = rb1; }
            float v0 = acc[im][in][0] + cb0;
            float v1 = acc[im][in][1] + cb1;
            float v2 = acc[im][in][2] + cb2;
            float v3 = acc[im][in][3] + cb3;
            *reinterpret_cast<__half2*>(Ch + (size_t)r0 * ldc + c) =
                __halves2half2(__float2half(v0), __float2half(v1));
            *reinterpret_cast<__half2*>(Ch + (size_t)r1 * ldc + c) =
                __halves2half2(__float2half(v2), __float2half(v3));
        }
    }
}

// ================= transpose + fp16 convert (hi only), optional channel-pool =================
template<typename T>
__device__ __forceinline__ void tconv_body(const T* src, __half* dh, int R, int C,
                                           float* pool_or_null) {
    __shared__ float t[64][33];
    __shared__ float ps[64];
    const int c0 = blockIdx.x * 32, r0 = blockIdx.y * 64;
    const int tx = threadIdx.x, ty = threadIdx.y;
    const int tid = ty * 32 + tx;
    if (pool_or_null && tid < 64) ps[tid] = 0.f;
    #pragma unroll
    for (int i = 0; i < 8; i++)
        t[ty + 8 * i][tx] = (float)src[(size_t)(r0 + ty + 8 * i) * C + c0 + tx];
    __syncthreads();
    float s0 = 0.f, s1 = 0.f;
    #pragma unroll
    for (int i = 0; i < 4; i++) {
        const int pixl = ty + 8 * i;
        float v0 = t[2 * tx][pixl], v1 = t[2 * tx + 1][pixl];
        size_t o = (size_t)(c0 + pixl) * R + r0 + 2 * tx;
        *reinterpret_cast<__half2*>(dh + o) = __floats2half2_rn(v0, v1);
        s0 += v0; s1 += v1;
    }
    if (pool_or_null) {
        __syncthreads();
        atomicAdd(&ps[2 * tx], s0);
        atomicAdd(&ps[2 * tx + 1], s1);
        __syncthreads();
        if (tid < 64) atomicAdd(&pool_or_null[r0 + tid], ps[tid]);
    }
}

__global__ void tconv_pair(const float* __restrict__ sA, __half* __restrict__ dA,
                           const float* __restrict__ sB, __half* __restrict__ dB,
                           int R, int C)
{
    const int sel = blockIdx.z & 1, b = blockIdx.z >> 1;
    const float* src = (sel ? sB : sA) + (size_t)b * R * C;
    __half* dh = (sel ? dB : dA) + (size_t)b * R * C;
    tconv_body<float>(src, dh, R, C, sel ? nullptr : (g_pool + b * NC));
}

__global__ void tconv1h(const __half* __restrict__ s, __half* __restrict__ d, int R, int C)
{
    tconv_body<__half>(s + (size_t)blockIdx.z * R * C, d + (size_t)blockIdx.z * R * C,
                       R, C, nullptr);
}

// ================= weight convert + scratch zeroing =================
__global__ void wsplit(const float* __restrict__ qw, const float* __restrict__ kvw,
                       const float* __restrict__ ow)
{
    int i = blockIdx.x * 256 + threadIdx.x;   // 0 .. 131071
    if (i < NB * NPIX) g_rowsum[i] = 0.f;
    if (i < NB * NC)   g_pool[i]   = 0.f;
    if (i < NC * NC) {
        g_qw_hi[i] = __float2half(qw[i]);
        g_ow_hi[i] = __float2half(ow[i]);
    }
    if (i < 2 * NC * NC) g_kvw_hi[i] = __float2half(kvw[i]);
}

// ================= gate MLP (tiny; consumes pooled sums) =================
__global__ __launch_bounds__(64)
void gate_mlp(const float* __restrict__ g1w, const float* __restrict__ g1b,
              const float* __restrict__ g2w, const float* __restrict__ g2b)
{
    const int b = blockIdx.x, tid = threadIdx.x;
    __shared__ float p[NC];
    for (int c = tid; c < NC; c += 64) p[c] = g_pool[b * NC + c] * (1.0f / NPIX);
    __syncthreads();
    __shared__ float hbuf[64];
    {
        float s = g1b[tid];
        #pragma unroll 4
        for (int c = 0; c < NC; c++) s = fmaf(g1w[tid * NC + c], p[c], s);
        hbuf[tid] = fmaxf(s, 0.f);
    }
    __syncthreads();
    if (tid == 0) {
        float s = g2b[0];
        #pragma unroll
        for (int o = 0; o < 64; o++) s = fmaf(g2w[o], hbuf[o], s);
        g_gate[b] = 1.f / (1.f + __expf(-s));
    }
}

// ================= dwconv3x3 + BN + SiLU -> local [c][n] fp16 (no O) =================
__global__ __launch_bounds__(256)
void local_kernel(const float* __restrict__ xs,
                  const float* __restrict__ dww, const float* __restrict__ dwb,
                  const float* __restrict__ bng, const float* __restrict__ bnb,
                  const float* __restrict__ bnm, const float* __restrict__ bnv)
{
    const int bc = blockIdx.x;
    const int c = bc & 255;
    const int tid = threadIdx.x;
    __shared__ float t[66 * 66];
    const float* x = xs + (size_t)bc * NPIX;
    for (int i = tid; i < 66 * 66; i += 256) {
        int h = i / 66 - 1, w = i % 66 - 1;
        t[i] = (h >= 0 && h < 64 && w >= 0 && w < 64) ? x[h * 64 + w] : 0.f;
    }
    float wt[9];
    #pragma unroll
    for (int k = 0; k < 9; k++) wt[k] = dww[c * 9 + k];
    float scale = bng[c] * rsqrtf(bnv[c] + 1e-5f);
    float shift = fmaf(dwb[c] - bnm[c], scale, bnb[c]);
    __half2* fptr2 = reinterpret_cast<__half2*>(g_fusedh + (size_t)bc * NPIX);
    __syncthreads();
    for (int i = tid; i < NPIX / 2; i += 256) {
        int i2 = 2 * i;
        int h = i2 >> 6, w = i2 & 63;
        const float* tp = &t[h * 66 + w];
        float conv0 = tp[0]   * wt[0] + tp[1]   * wt[1] + tp[2]   * wt[2]
                    + tp[66]  * wt[3] + tp[67]  * wt[4] + tp[68]  * wt[5]
                    + tp[132] * wt[6] + tp[133] * wt[7] + tp[134] * wt[8];
        float conv1 = tp[1]   * wt[0] + tp[2]   * wt[1] + tp[3]   * wt[2]
                    + tp[67]  * wt[3] + tp[68]  * wt[4] + tp[69]  * wt[5]
                    + tp[133] * wt[6] + tp[134] * wt[7] + tp[135] * wt[8];
        float y0 = fmaf(conv0, scale, shift);
        float y1 = fmaf(conv1, scale, shift);
        float lf0 = y0 / (1.f + __expf(-y0));
        float lf1 = y1 / (1.f + __expf(-y1));
        fptr2[i] = __floats2half2_rn(lf0, lf1);
    }
}

// ================= launch =================
extern "C" void kernel_launch(void* const* d_in, const int* in_sizes, int n_in,
                              void* d_out, int out_size)
{
    const float* x_self  = (const float*)d_in[0];
    const float* x_other = (const float*)d_in[1];
    const float* q_w  = (const float*)d_in[2];
    const float* q_b  = (const float*)d_in[3];
    const float* kv_w = (const float*)d_in[4];
    const float* kv_b = (const float*)d_in[5];
    const float* g1_w = (const float*)d_in[6];
    const float* g1_b = (const float*)d_in[7];
    const float* g2_w = (const float*)d_in[8];
    const float* g2_b = (const float*)d_in[9];
    const float* dw_w = (const float*)d_in[10];
    const float* dw_b = (const float*)d_in[11];
    const float* bn_g = (const float*)d_in[12];
    const float* bn_b = (const float*)d_in[13];
    const float* bn_m = (const float*)d_in[14];
    const float* bn_v = (const float*)d_in[15];
    const float* out_w = (const float*)d_in[16];
    const float* out_b = (const float*)d_in[17];
    float* out = (float*)d_out;

    cudaFuncSetAttribute(proj_gemm,       cudaFuncAttributeMaxDynamicSharedMemorySize, SMTOT1);
    cudaFuncSetAttribute(mma_gemm<0, 3>,  cudaFuncAttributeMaxDynamicSharedMemorySize, SMTOT1);
    cudaFuncSetAttribute(mma_gemm<3, 4>,  cudaFuncAttributeMaxDynamicSharedMemorySize, SMTOT1);
    cudaFuncSetAttribute(mma_gemm<1, 0>,  cudaFuncAttributeMaxDynamicSharedMemorySize, SMTOT1);

    #define SYM(p, s) cudaGetSymbolAddress((void**)&p, s)
    __half *xsh, *xoh, *qth, *kth, *vh, *ph, *fph, *fth, *qwh, *kvwh, *owh;
    SYM(xsh, g_xs_hi); SYM(xoh, g_xo_hi);
    SYM(qth, g_qt_hi); SYM(kth, g_kt_hi); SYM(vh, g_v_hi);   SYM(ph, g_p);
    SYM(fph, g_fusedh); SYM(fth, g_ft_hi);
    SYM(qwh, g_qw_hi); SYM(kvwh, g_kvw_hi); SYM(owh, g_ow_hi);
    #undef SYM

    const long long sX = (long long)NPIX * NC;
    const long long sS = (long long)NPIX * NPIX;

    wsplit<<<2 * NC * NC / 256, 256>>>(q_w, kv_w, out_w);   // also zeroes pool/rowsum
    tconv_pair<<<dim3(NPIX / 32, NC / 64, 2 * NB), dim3(32, 8)>>>(
        x_self, xsh, x_other, xoh, NC, NPIX);               // also pools x_self
    gate_mlp<<<NB, 64>>>(g1_w, g1_b, g2_w, g2_b);

    // local_feat = SiLU(BN(dwconv(x_self))) -> g_fusedh  (independent of attention)
    local_kernel<<<NB * NC, 256>>>(x_self, dw_w, dw_b, bn_g, bn_b, bn_m, bn_v);

    // Q/K/V projections in one launch (768 CTAs)
    proj_gemm<<<dim3(64, 1, 12), 256, SMTOT1>>>(
        xsh, xoh, qwh, kvwh, q_b, kv_b, qth, kth, vh);

    // P[n][m] = exp((1/16) Qt·Kt^T) fp16 + row sums
    mma_gemm<0, 3><<<dim3(32, 32, NB), 256, SMTOT1>>>(
        qth, kth, nullptr, 0.0625f, nullptr, ph, NC, NPIX, sX, sX, sS);

    // fused[c][n] = local[c][n] + gate * (sum_m V[c][m] P[n][m]) / rowsum[n]   (in place)
    mma_gemm<3, 4><<<dim3(32, 2, NB), 256, SMTOT1>>>(
        vh, ph, nullptr, 1.f, nullptr, fph, NPIX, NPIX, sX, sS, sX);

    tconv1h<<<dim3(NPIX / 32, NC / 64, NB), dim3(32, 8)>>>(fph, fth, NC, NPIX);

    // out[o][n] = sum_c ow[o][c] ft[n][c] + out_b[o]   (fp32, row bias)
    mma_gemm<1, 0><<<dim3(32, 2, NB), 256, SMTOT1>>>(
        owh, fth, out_b, 1.f, out, nullptr, NC, NPIX, 0, sX, sX);
}